// round 1
// baseline (speedup 1.0000x reference)
#include <cuda_runtime.h>
#include <math.h>

#define B 4096
#define D 256
#define NC 2
#define NR 4
#define TEMP_INV 10.0f

// -------- scratch (static device globals; no runtime allocation) ----------
__device__ float g_pn[B * D];              // normalized projections (4 MB)
__device__ float g_sim[(size_t)B * B];     // similarity matrix (64 MB)
__device__ float g_lse[B];                 // per-row negative logsumexp
__device__ float g_acc[8];                 // 0 focal,1 pd_cnt,2 ct_cnt,3 pdS,4 ctS,5 ce,6 cont

// -------- helpers ----------------------------------------------------------
__device__ __forceinline__ float block_reduce_sum(float v, float* sh) {
    int t = threadIdx.x;
    sh[t] = v;
    __syncthreads();
    for (int s = blockDim.x >> 1; s > 0; s >>= 1) {
        if (t < s) sh[t] += sh[t + s];
        __syncthreads();
    }
    float r = sh[0];
    __syncthreads();
    return r;
}

// -------- 0: zero accumulators --------------------------------------------
__global__ void init_kernel() {
    if (threadIdx.x < 8) g_acc[threadIdx.x] = 0.0f;
}

// -------- 1: row-normalize projections (1 warp / row) ----------------------
__global__ void normalize_kernel(const float* __restrict__ proj) {
    int row  = blockIdx.x * 8 + (threadIdx.x >> 5);
    int lane = threadIdx.x & 31;
    const float* src = proj + (size_t)row * D;
    float v[8];
    float ss = 0.0f;
#pragma unroll
    for (int k = 0; k < 8; k++) {
        v[k] = src[lane + 32 * k];
        ss += v[k] * v[k];
    }
#pragma unroll
    for (int o = 16; o > 0; o >>= 1) ss += __shfl_xor_sync(0xFFFFFFFFu, ss, o);
    float inv = 1.0f / fmaxf(sqrtf(ss), 1e-12f);
    float* dst = g_pn + (size_t)row * D;
#pragma unroll
    for (int k = 0; k < 8; k++) dst[lane + 32 * k] = v[k] * inv;
}

// -------- 2: sim GEMM, symmetric tiles only (128x128x16, 8x8/thread) -------
#define BM 128
#define BK 16
__global__ __launch_bounds__(256) void sim_kernel() {
    int bi = blockIdx.y, bj = blockIdx.x;
    if (bi > bj) return;  // exploit symmetry

    __shared__ float As[BK][BM + 4];
    __shared__ float Bs[BK][BM + 4];

    int t  = threadIdx.x;
    int tx = t & 15, ty = t >> 4;
    int rowA = bi * BM, rowB = bj * BM;

    float acc[8][8];
#pragma unroll
    for (int u = 0; u < 8; u++)
#pragma unroll
        for (int v = 0; v < 8; v++) acc[u][v] = 0.0f;

    for (int k0 = 0; k0 < D; k0 += BK) {
#pragma unroll
        for (int l = 0; l < 8; l++) {
            int idx = t + 256 * l;
            int r = idx >> 4, c = idx & 15;
            As[c][r] = g_pn[(size_t)(rowA + r) * D + k0 + c];
            Bs[c][r] = g_pn[(size_t)(rowB + r) * D + k0 + c];
        }
        __syncthreads();
#pragma unroll
        for (int kk = 0; kk < BK; kk++) {
            float a[8], b[8];
#pragma unroll
            for (int u = 0; u < 8; u++) a[u] = As[kk][ty * 8 + u];
#pragma unroll
            for (int v = 0; v < 8; v++) b[v] = Bs[kk][tx * 8 + v];
#pragma unroll
            for (int u = 0; u < 8; u++)
#pragma unroll
                for (int v = 0; v < 8; v++) acc[u][v] = fmaf(a[u], b[v], acc[u][v]);
        }
        __syncthreads();
    }

#pragma unroll
    for (int u = 0; u < 8; u++) {
        int gi = rowA + ty * 8 + u;
#pragma unroll
        for (int v = 0; v < 8; v++) {
            int gj = rowB + tx * 8 + v;
            float val = acc[u][v] * TEMP_INV;
            if (gi == gj) val = -1e9f;
            g_sim[(size_t)gi * B + gj] = val;
            if (bi < bj) g_sim[(size_t)gj * B + gi] = val;
        }
    }
}

// -------- 3: per-row masked logsumexp over negatives -----------------------
__global__ void lse_kernel(const int* __restrict__ labels) {
    int i  = blockIdx.x;
    int li = labels[i];
    const float* row = g_sim + (size_t)i * B;

    float m = -INFINITY, s = 0.0f;
    for (int j = threadIdx.x; j < B; j += blockDim.x) {
        if (j != i && labels[j] == li) continue;  // exclude positives
        float v = row[j];                          // diag already -1e9
        if (v > m) {
            s = s * expf(m - v) + 1.0f;
            m = v;
        } else {
            s += expf(v - m);
        }
    }

    __shared__ float sm[256], ss_[256];
    sm[threadIdx.x] = m;
    ss_[threadIdx.x] = s;
    __syncthreads();
    for (int st = 128; st > 0; st >>= 1) {
        if (threadIdx.x < st) {
            float m1 = sm[threadIdx.x],      s1 = ss_[threadIdx.x];
            float m2 = sm[threadIdx.x + st], s2 = ss_[threadIdx.x + st];
            float M = fmaxf(m1, m2);
            float S = 0.0f;
            if (m1 > -INFINITY) S += s1 * expf(m1 - M);
            if (m2 > -INFINITY) S += s2 * expf(m2 - M);
            sm[threadIdx.x] = M;
            ss_[threadIdx.x] = S;
        }
        __syncthreads();
    }
    if (threadIdx.x == 0) g_lse[i] = sm[0] + logf(ss_[0]);
}

// -------- 4: sum per-pair contrastive terms over positives -----------------
__global__ void pair_kernel(const int* __restrict__ labels) {
    const size_t N = (size_t)B * B;
    float local = 0.0f;
    for (size_t idx = (size_t)blockIdx.x * blockDim.x + threadIdx.x; idx < N;
         idx += (size_t)gridDim.x * blockDim.x) {
        int i = (int)(idx >> 12);
        int j = (int)(idx & (B - 1));
        if (i != j && labels[i] == labels[j]) {
            float d = g_lse[i] - g_sim[idx];
            local += log1pf(expf(d));  // logaddexp(sim, lse) - sim
        }
    }
    __shared__ float sh[256];
    float tot = block_reduce_sum(local, sh);
    if (threadIdx.x == 0) atomicAdd(&g_acc[6], tot);
}

// -------- 5: focal + region losses (one pass over B) -----------------------
__global__ void small_kernel(const float* __restrict__ logits,
                             const float* __restrict__ rp,
                             const int* __restrict__ labels) {
    int b = blockIdx.x * blockDim.x + threadIdx.x;
    float focal = 0, Spd = 0, Sct = 0, ce_sum = 0, cpd = 0, cct = 0;
    if (b < B) {
        int y = labels[b];
        // focal on logits/1.5, gamma=2
        float z0 = logits[2 * b] / 1.5f, z1 = logits[2 * b + 1] / 1.5f;
        float m  = fmaxf(z0, z1);
        float l  = m + logf(expf(z0 - m) + expf(z1 - m));
        float ce = l - (y ? z1 : z0);
        float pt = expf(-ce);
        float om = 1.0f - pt;
        focal = om * om * ce;
        if (y) cpd = 1.0f; else cct = 1.0f;

        // region loss: S_b = sum_{i<j} [ ent_j - sum_c p_j,c * log(p_i,c + 1e-10) ]
        float p[NR][2], le[NR][2], ent[NR];
#pragma unroll
        for (int r = 0; r < NR; r++) {
            float a0 = rp[((size_t)r * B + b) * 2];
            float a1 = rp[((size_t)r * B + b) * 2 + 1];
            float mm = fmaxf(a0, a1);
            float ll = mm + logf(expf(a0 - mm) + expf(a1 - mm));
            float lp0 = a0 - ll, lp1 = a1 - ll;
            p[r][0] = expf(lp0);
            p[r][1] = expf(lp1);
            le[r][0] = logf(p[r][0] + 1e-10f);
            le[r][1] = logf(p[r][1] + 1e-10f);
            ent[r] = p[r][0] * lp0 + p[r][1] * lp1;
            ce_sum += -(y ? lp1 : lp0);
        }
        float S = 0.0f;
#pragma unroll
        for (int i = 0; i < NR; i++)
#pragma unroll
            for (int j = i + 1; j < NR; j++)
                S += ent[j] - (p[j][0] * le[i][0] + p[j][1] * le[i][1]);
        if (y) Spd = S; else Sct = S;
    }
    __shared__ float sh[256];
    float t;
    t = block_reduce_sum(focal, sh);  if (threadIdx.x == 0) atomicAdd(&g_acc[0], t);
    t = block_reduce_sum(cpd, sh);    if (threadIdx.x == 0) atomicAdd(&g_acc[1], t);
    t = block_reduce_sum(cct, sh);    if (threadIdx.x == 0) atomicAdd(&g_acc[2], t);
    t = block_reduce_sum(Spd, sh);    if (threadIdx.x == 0) atomicAdd(&g_acc[3], t);
    t = block_reduce_sum(Sct, sh);    if (threadIdx.x == 0) atomicAdd(&g_acc[4], t);
    t = block_reduce_sum(ce_sum, sh); if (threadIdx.x == 0) atomicAdd(&g_acc[5], t);
}

// -------- 6: combine -------------------------------------------------------
__global__ void finalize_kernel(float* __restrict__ out) {
    float focal = g_acc[0] / (float)B;
    float pd_cnt = g_acc[1], ct_cnt = g_acc[2];
    float pd = (pd_cnt > 0.0f) ? g_acc[3] / pd_cnt : 0.0f;
    float ct = (ct_cnt > 0.0f) ? g_acc[4] / ct_cnt : 0.0f;
    float ce = g_acc[5] / (float)B;
    float reg = (pd + ct + ce) / ((float)(NR * (NR - 1)) * 0.5f + (float)NR);
    float cont = g_acc[6] / (float)B;
    out[0] = 1.0f * focal + 0.5f * cont + 0.3f * reg;
}

// -------- launch -----------------------------------------------------------
extern "C" void kernel_launch(void* const* d_in, const int* in_sizes, int n_in,
                              void* d_out, int out_size) {
    const float* logits = (const float*)d_in[0];
    const float* proj   = (const float*)d_in[1];
    const float* rp     = (const float*)d_in[2];
    const int*   labels = (const int*)d_in[3];
    float* out = (float*)d_out;
    (void)in_sizes; (void)n_in; (void)out_size;

    init_kernel<<<1, 32>>>();
    normalize_kernel<<<B / 8, 256>>>(proj);
    small_kernel<<<B / 256, 256>>>(logits, rp, labels);
    {
        dim3 grid(B / BM, B / BM);
        sim_kernel<<<grid, 256>>>();
    }
    lse_kernel<<<B, 256>>>(labels);
    pair_kernel<<<2048, 256>>>(labels);
    finalize_kernel<<<1, 1>>>(out);
}

// round 2
// speedup vs baseline: 1.9097x; 1.9097x over previous
#include <cuda_runtime.h>
#include <math.h>
#include <stdint.h>

#define B 4096
#define D 256
#define NR 4
#define TEMP_INV 10.0f
#define TILE 128

// -------- scratch (static device globals) ----------------------------------
__device__ float g_pn[B * D];              // tf32-rounded normalized projections
__device__ float g_sim[(size_t)B * B];     // similarity matrix (64 MB)
__device__ float g_acc[8];                 // 0 focal,1 pd_cnt,2 ct_cnt,3 pdS,4 ctS,5 ce,6 cont

// -------- helpers ----------------------------------------------------------
__device__ __forceinline__ float block_reduce_sum(float v, float* sh) {
    int t = threadIdx.x;
    sh[t] = v;
    __syncthreads();
    for (int s = blockDim.x >> 1; s > 0; s >>= 1) {
        if (t < s) sh[t] += sh[t + s];
        __syncthreads();
    }
    float r = sh[0];
    __syncthreads();
    return r;
}

__device__ __forceinline__ uint32_t f2tf32(float x) {
    uint32_t r;
    asm("cvt.rna.tf32.f32 %0, %1;" : "=r"(r) : "f"(x));
    return r;
}

__device__ __forceinline__ void mma_tf32(float c[4], const uint32_t a[4],
                                         uint32_t b0, uint32_t b1) {
    asm volatile(
        "mma.sync.aligned.m16n8k8.row.col.f32.tf32.tf32.f32 "
        "{%0,%1,%2,%3}, {%4,%5,%6,%7}, {%8,%9}, {%0,%1,%2,%3};\n"
        : "+f"(c[0]), "+f"(c[1]), "+f"(c[2]), "+f"(c[3])
        : "r"(a[0]), "r"(a[1]), "r"(a[2]), "r"(a[3]), "r"(b0), "r"(b1));
}

// -------- 0: zero accumulators --------------------------------------------
__global__ void init_kernel() {
    if (threadIdx.x < 8) g_acc[threadIdx.x] = 0.0f;
}

// -------- 1: row-normalize projections, round to tf32 ----------------------
__global__ void normalize_kernel(const float* __restrict__ proj) {
    int row  = blockIdx.x * 8 + (threadIdx.x >> 5);
    int lane = threadIdx.x & 31;
    const float* src = proj + (size_t)row * D;
    float v[8];
    float ss = 0.0f;
#pragma unroll
    for (int k = 0; k < 8; k++) {
        v[k] = src[lane + 32 * k];
        ss += v[k] * v[k];
    }
#pragma unroll
    for (int o = 16; o > 0; o >>= 1) ss += __shfl_xor_sync(0xFFFFFFFFu, ss, o);
    float inv = 1.0f / fmaxf(sqrtf(ss), 1e-12f);
    float* dst = g_pn + (size_t)row * D;
#pragma unroll
    for (int k = 0; k < 8; k++) dst[lane + 32 * k] = __uint_as_float(f2tf32(v[k] * inv));
}

// -------- 2: sim GEMM on tensor cores (tf32 mma.sync), symmetric tiles -----
// Block tile 128x128, 8 warps (4 row-warps x 2 col-warps), warp tile 32x64.
#define APAD 17
__global__ __launch_bounds__(256) void sim_kernel() {
    int bi = blockIdx.y, bj = blockIdx.x;
    if (bi > bj) return;

    __shared__ float shbuf[2 * TILE * APAD];  // As | Bs, reused for transpose staging
#define AS(r, c) shbuf[(r) * APAD + (c)]
#define BS(r, c) shbuf[TILE * APAD + (r) * APAD + (c)]
#define ST(cc, r) shbuf[(cc) * 129 + (r)]

    int t = threadIdx.x, lane = t & 31, warp = t >> 5;
    int wr = warp & 3, wc = warp >> 2;
    int tig = lane & 3, grp = lane >> 2;
    int rowA = bi * TILE, rowB = bj * TILE;

    float c[2][8][4];
#pragma unroll
    for (int mt = 0; mt < 2; mt++)
#pragma unroll
        for (int nt = 0; nt < 8; nt++)
#pragma unroll
            for (int q = 0; q < 4; q++) c[mt][nt][q] = 0.0f;

    const float4* p4 = (const float4*)g_pn;

    for (int k0 = 0; k0 < D; k0 += 16) {
#pragma unroll
        for (int l = 0; l < 2; l++) {
            int idx = t + 256 * l;          // 512 float4 per tile
            int r = idx >> 2, cf = idx & 3; // 4 float4 per row of 16
            float4 va = p4[(size_t)(rowA + r) * (D / 4) + (k0 >> 2) + cf];
            AS(r, cf * 4 + 0) = va.x; AS(r, cf * 4 + 1) = va.y;
            AS(r, cf * 4 + 2) = va.z; AS(r, cf * 4 + 3) = va.w;
            float4 vb = p4[(size_t)(rowB + r) * (D / 4) + (k0 >> 2) + cf];
            BS(r, cf * 4 + 0) = vb.x; BS(r, cf * 4 + 1) = vb.y;
            BS(r, cf * 4 + 2) = vb.z; BS(r, cf * 4 + 3) = vb.w;
        }
        __syncthreads();
#pragma unroll
        for (int ks = 0; ks < 2; ks++) {
            int kb = ks * 8;
            uint32_t a[2][4];
#pragma unroll
            for (int mt = 0; mt < 2; mt++) {
                int r = wr * 32 + mt * 16 + grp;
                a[mt][0] = __float_as_uint(AS(r,     kb + tig));
                a[mt][1] = __float_as_uint(AS(r + 8, kb + tig));
                a[mt][2] = __float_as_uint(AS(r,     kb + tig + 4));
                a[mt][3] = __float_as_uint(AS(r + 8, kb + tig + 4));
            }
#pragma unroll
            for (int nt = 0; nt < 8; nt++) {
                int bn = wc * 64 + nt * 8 + grp;
                uint32_t b0 = __float_as_uint(BS(bn, kb + tig));
                uint32_t b1 = __float_as_uint(BS(bn, kb + tig + 4));
                mma_tf32(c[0][nt], a[0], b0, b1);
                mma_tf32(c[1][nt], a[1], b0, b1);
            }
        }
        __syncthreads();
    }

    // scale by 1/temp
#pragma unroll
    for (int mt = 0; mt < 2; mt++)
#pragma unroll
        for (int nt = 0; nt < 8; nt++)
#pragma unroll
            for (int q = 0; q < 4; q++) c[mt][nt][q] *= TEMP_INV;

    // direct (coalesced, float2) write of this tile, with diagonal masking
#pragma unroll
    for (int mt = 0; mt < 2; mt++) {
        int gi0 = rowA + wr * 32 + mt * 16 + grp;
#pragma unroll
        for (int nt = 0; nt < 8; nt++) {
            int gj = rowB + wc * 64 + nt * 8 + 2 * tig;
            float2 v01 = make_float2(c[mt][nt][0], c[mt][nt][1]);
            float2 v23 = make_float2(c[mt][nt][2], c[mt][nt][3]);
            if (bi == bj) {
                if (gi0 == gj)         v01.x = -1e9f;
                if (gi0 == gj + 1)     v01.y = -1e9f;
                if (gi0 + 8 == gj)     v23.x = -1e9f;
                if (gi0 + 8 == gj + 1) v23.y = -1e9f;
            }
            *(float2*)&g_sim[(size_t)gi0 * B + gj]       = v01;
            *(float2*)&g_sim[(size_t)(gi0 + 8) * B + gj] = v23;
        }
    }

    // mirror write (transposed) through shared, 32-column chunks, coalesced
    if (bi < bj) {
        __syncthreads();  // done with As/Bs contents
#pragma unroll
        for (int chunk = 0; chunk < 4; chunk++) {
            if ((chunk >> 1) == wc) {
#pragma unroll
                for (int mt = 0; mt < 2; mt++) {
                    int r = wr * 32 + mt * 16 + grp;
#pragma unroll
                    for (int q = 0; q < 4; q++) {
                        int nt = (chunk & 1) * 4 + q;
                        int cc = q * 8 + 2 * tig;
                        ST(cc, r)         = c[mt][nt][0];
                        ST(cc + 1, r)     = c[mt][nt][1];
                        ST(cc, r + 8)     = c[mt][nt][2];
                        ST(cc + 1, r + 8) = c[mt][nt][3];
                    }
                }
            }
            __syncthreads();
            for (int e = t; e < 32 * 128; e += 256) {
                int cc = e >> 7, r = e & 127;
                g_sim[(size_t)(rowB + chunk * 32 + cc) * B + rowA + r] = ST(cc, r);
            }
            __syncthreads();
        }
    }
#undef AS
#undef BS
#undef ST
}

// -------- 3: fused masked-LSE + positive-pair sum (one 64MB pass) ----------
__global__ __launch_bounds__(256) void lse_pair_kernel(const int* __restrict__ labels) {
    int i = blockIdx.x;
    int li = labels[i];
    const float* row = g_sim + (size_t)i * B;

    float v[16];
    unsigned pm = 0;
    float m = -INFINITY, s = 0.0f;
#pragma unroll
    for (int k = 0; k < 16; k++) {
        int j = threadIdx.x + (k << 8);
        float x = row[j];
        v[k] = x;
        if (j != i && labels[j] == li) {
            pm |= (1u << k);  // positive: excluded from LSE, used in pair sum
        } else {
            if (x > m) { s = s * expf(m - x) + 1.0f; m = x; }
            else        s += expf(x - m);
        }
    }

    __shared__ float sm[256], ss[256];
    sm[threadIdx.x] = m;
    ss[threadIdx.x] = s;
    __syncthreads();
    for (int st = 128; st > 0; st >>= 1) {
        if (threadIdx.x < st) {
            float m1 = sm[threadIdx.x],      s1 = ss[threadIdx.x];
            float m2 = sm[threadIdx.x + st], s2 = ss[threadIdx.x + st];
            float M = fmaxf(m1, m2);
            float S = 0.0f;
            if (m1 > -INFINITY) S += s1 * expf(m1 - M);
            if (m2 > -INFINITY) S += s2 * expf(m2 - M);
            sm[threadIdx.x] = M;
            ss[threadIdx.x] = S;
        }
        __syncthreads();
    }
    __shared__ float lse_sh;
    if (threadIdx.x == 0) lse_sh = sm[0] + logf(ss[0]);
    __syncthreads();
    float lse = lse_sh;

    float acc = 0.0f;
#pragma unroll
    for (int k = 0; k < 16; k++)
        if (pm & (1u << k)) acc += log1pf(expf(lse - v[k]));

    float tot = block_reduce_sum(acc, sm);
    if (threadIdx.x == 0) atomicAdd(&g_acc[6], tot);
}

// -------- 4: focal + region losses (one pass over B) -----------------------
__global__ void small_kernel(const float* __restrict__ logits,
                             const float* __restrict__ rp,
                             const int* __restrict__ labels) {
    int b = blockIdx.x * blockDim.x + threadIdx.x;
    float focal = 0, Spd = 0, Sct = 0, ce_sum = 0, cpd = 0, cct = 0;
    if (b < B) {
        int y = labels[b];
        float z0 = logits[2 * b] / 1.5f, z1 = logits[2 * b + 1] / 1.5f;
        float m  = fmaxf(z0, z1);
        float l  = m + logf(expf(z0 - m) + expf(z1 - m));
        float ce = l - (y ? z1 : z0);
        float pt = expf(-ce);
        float om = 1.0f - pt;
        focal = om * om * ce;
        if (y) cpd = 1.0f; else cct = 1.0f;

        float p[NR][2], le[NR][2], ent[NR];
#pragma unroll
        for (int r = 0; r < NR; r++) {
            float a0 = rp[((size_t)r * B + b) * 2];
            float a1 = rp[((size_t)r * B + b) * 2 + 1];
            float mm = fmaxf(a0, a1);
            float ll = mm + logf(expf(a0 - mm) + expf(a1 - mm));
            float lp0 = a0 - ll, lp1 = a1 - ll;
            p[r][0] = expf(lp0);
            p[r][1] = expf(lp1);
            le[r][0] = logf(p[r][0] + 1e-10f);
            le[r][1] = logf(p[r][1] + 1e-10f);
            ent[r] = p[r][0] * lp0 + p[r][1] * lp1;
            ce_sum += -(y ? lp1 : lp0);
        }
        float S = 0.0f;
#pragma unroll
        for (int i = 0; i < NR; i++)
#pragma unroll
            for (int j = i + 1; j < NR; j++)
                S += ent[j] - (p[j][0] * le[i][0] + p[j][1] * le[i][1]);
        if (y) Spd = S; else Sct = S;
    }
    __shared__ float sh[256];
    float t;
    t = block_reduce_sum(focal, sh);  if (threadIdx.x == 0) atomicAdd(&g_acc[0], t);
    t = block_reduce_sum(cpd, sh);    if (threadIdx.x == 0) atomicAdd(&g_acc[1], t);
    t = block_reduce_sum(cct, sh);    if (threadIdx.x == 0) atomicAdd(&g_acc[2], t);
    t = block_reduce_sum(Spd, sh);    if (threadIdx.x == 0) atomicAdd(&g_acc[3], t);
    t = block_reduce_sum(Sct, sh);    if (threadIdx.x == 0) atomicAdd(&g_acc[4], t);
    t = block_reduce_sum(ce_sum, sh); if (threadIdx.x == 0) atomicAdd(&g_acc[5], t);
}

// -------- 5: combine -------------------------------------------------------
__global__ void finalize_kernel(float* __restrict__ out) {
    float focal = g_acc[0] / (float)B;
    float pd_cnt = g_acc[1], ct_cnt = g_acc[2];
    float pd = (pd_cnt > 0.0f) ? g_acc[3] / pd_cnt : 0.0f;
    float ct = (ct_cnt > 0.0f) ? g_acc[4] / ct_cnt : 0.0f;
    float ce = g_acc[5] / (float)B;
    float reg = (pd + ct + ce) / ((float)(NR * (NR - 1)) * 0.5f + (float)NR);
    float cont = g_acc[6] / (float)B;
    out[0] = 1.0f * focal + 0.5f * cont + 0.3f * reg;
}

// -------- launch -----------------------------------------------------------
extern "C" void kernel_launch(void* const* d_in, const int* in_sizes, int n_in,
                              void* d_out, int out_size) {
    const float* logits = (const float*)d_in[0];
    const float* proj   = (const float*)d_in[1];
    const float* rp     = (const float*)d_in[2];
    const int*   labels = (const int*)d_in[3];
    float* out = (float*)d_out;
    (void)in_sizes; (void)n_in; (void)out_size;

    init_kernel<<<1, 32>>>();
    normalize_kernel<<<B / 8, 256>>>(proj);
    small_kernel<<<B / 256, 256>>>(logits, rp, labels);
    sim_kernel<<<dim3(B / TILE, B / TILE), 256>>>();
    lse_pair_kernel<<<B, 256>>>(labels);
    finalize_kernel<<<1, 1>>>(out);
}